// round 6
// baseline (speedup 1.0000x reference)
#include <cuda_runtime.h>

#define S_LEN 512
#define BATCH 512
#define HD    128            // H*d
#define NB    4              // batch rows per block (1 per group)
#define NTHR  512            // 4 k-groups x 128 outputs
#define KQ    32             // k-slices per group
#define EPSF  1e-15f
#define PEF   1e-5f          // PROJ_EPS

// ---------------- packed f32x2 helpers ----------------
__device__ __forceinline__ unsigned long long pack2f(float lo, float hi) {
    unsigned long long r;
    asm("mov.b64 %0, {%1, %2};" : "=l"(r) : "r"(__float_as_uint(lo)), "r"(__float_as_uint(hi)));
    return r;
}
__device__ __forceinline__ void unpack2f(unsigned long long p, float &lo, float &hi) {
    unsigned a, b;
    asm("mov.b64 {%0, %1}, %2;" : "=r"(a), "=r"(b) : "l"(p));
    lo = __uint_as_float(a);
    hi = __uint_as_float(b);
}
__device__ __forceinline__ unsigned long long fma2(unsigned long long a,
                                                   unsigned long long b,
                                                   unsigned long long c) {
    unsigned long long d;
    asm("fma.rn.f32x2 %0, %1, %2, %3;" : "=l"(d) : "l"(a), "l"(b), "l"(c));
    return d;
}
__device__ __forceinline__ unsigned long long add2(unsigned long long a,
                                                   unsigned long long b) {
    unsigned long long d;
    asm("add.rn.f32x2 %0, %1, %2;" : "=l"(d) : "l"(a), "l"(b));
    return d;
}

// ---------------- Mobius math (head = 2 elems, partner via shfl.xor 1) -------
__device__ __forceinline__ void project2(float &a, float &b) {
    float n2 = fmaf(a, a, b * b);
    float sc = (1.0f - PEF) * __fdividef(1.0f, fmaxf(n2, 1.0f - PEF));
    a *= sc;
    b *= sc;
}

// project own component; return projected value, set ||proj_head + EPS||
__device__ __forceinline__ float stage_proj(float v, float &norm_out) {
    float q  = __shfl_xor_sync(0xffffffffu, v, 1);
    float n2 = fmaf(v, v, q * q);
    float sc = (1.0f - PEF) * __fdividef(1.0f, fmaxf(n2, 1.0f - PEF));
    float p  = v * sc;
    float pq = q * sc;
    float a0 = p + EPSF, a1 = pq + EPSF;
    norm_out = __fsqrt_rn(fmaf(a0, a0, a1 * a1));
    return p;
}

// mob_mat_mul epilogue. m = own accumulator component, xn = input-head norm.
__device__ __forceinline__ void mmm_post(float m, float xn, float &o0, float &o1) {
    float mp   = __shfl_xor_sync(0xffffffffu, m, 1);
    float a0   = m + EPSF, a1 = mp + EPSF;
    float n2m  = fmaf(a0, a0, a1 * a1);
    float invm = rsqrtf(n2m);
    float Mxn  = n2m * invm;                                        // ||Mx+EPS||
    float r    = __fdividef(Mxn, xn);
    float at   = 0.5f * __logf(__fdividef(1.0f + xn, 1.0f - xn));   // atanh(xn)
    float z    = r * at;
    float e2   = __expf(2.0f * z);
    float t    = 1.0f - __fdividef(2.0f, e2 + 1.0f);                // tanh(z)
    float sc   = t * invm;
    o0 = sc * m;
    o1 = sc * mp;
    project2(o0, o1);
}

__device__ __forceinline__ void mob_add2(float u0, float u1, float v0, float v1,
                                         float &o0, float &o1) {
    v0 += EPSF; v1 += EPSF;
    float nuv = 2.0f * fmaf(u0, v0, u1 * v1);
    float nu  = fmaf(u0, u0, u1 * u1);
    float nv  = fmaf(v0, v0, v1 * v1);
    float idn = __fdividef(1.0f, 1.0f + nuv + nv * nu);
    float cA  = (1.0f + nuv + nv) * idn;
    float cB  = (1.0f - nu) * idn;
    o0 = cA * u0 + cB * v0;
    o1 = cA * u1 + cB * v1;
    project2(o0, o1);
}

// full per-row epilogue: h_new_own = mob_add(mob_add(Wh, Ux), b)
__device__ __forceinline__ float step_row(float wm, float hn, float um, float xn,
                                          float bia, float bip) {
    float w0, w1, u0, u1, s0, s1, o0, o1;
    mmm_post(wm, hn, w0, w1);
    mmm_post(um, xn, u0, u1);
    mob_add2(w0, w1, u0, u1, s0, s1);
    mob_add2(s0, s1, bia, bip, o0, o1);
    return o0;
}

// ---------------- kernel ----------------
// 512 threads: g = tid>>7 in {0..3} (k-group AND owned row), e = tid&127.
// Thread (g,e):
//   - packed weights {W[k][e],U[k][e]} for k in [32g, 32g+32) in regs (64 regs)
//   - owns state row g: staging (projection + norms) and full epilogue
//   - matvec partial over its k-quarter for ALL 4 rows (4 FFMA2 chains)
//   - partial exchange through smem, 4-way reduce for own row
// Staged smem: s01[k] = {h0,x0,h1,x1} (projected), s23[k] = {h2,x2,h3,x3}.
__global__ void __launch_bounds__(NTHR, 1)
hyper_rnn_kernel(const float *__restrict__ xg,   // [B,S,HD]
                 const float *__restrict__ wg,   // [HD,HD] (k, e)
                 const float *__restrict__ ug,
                 const float *__restrict__ bg,   // [HD]
                 float *__restrict__ yg)         // [B,S,HD]
{
    __shared__ ulonglong2 s01[HD];
    __shared__ ulonglong2 s23[HD];
    __shared__ ulonglong2 ps[4][HD][2];   // [srcgroup][e][{rows01,rows23}]

    const int tid = threadIdx.x;
    const int g   = tid >> 7;          // k-quarter and owned row
    const int e   = tid & (HD - 1);
    const int b0  = blockIdx.x * NB;

    // packed {W,U} weight column slice -> registers (one-time)
    unsigned long long wu[KQ];
#pragma unroll
    for (int j = 0; j < KQ; ++j) {
        int k = g * KQ + j;
        wu[j] = pack2f(wg[k * HD + e], ug[k * HD + e]);
    }

    float bia = bg[e];
    float bip = __shfl_xor_sync(0xffffffffu, bia, 1);

    float h = 0.0f;                    // state row g
    float x = xg[((size_t)(b0 + g) * S_LEN) * HD + e];

    // staging slot for row g: component g of the {h,x} interleave
    unsigned long long *slot = (g < 2)
        ? ((unsigned long long *)s01) + 2 * e + g
        : ((unsigned long long *)s23) + 2 * e + (g - 2);

    for (int s = 0; s < S_LEN; ++s) {
        // ---- stage own row: project h and x, norms stay in regs ----
        float hn, xn;
        float hp = stage_proj(h, hn);
        float xp = stage_proj(x, xn);
        *slot = pack2f(hp, xp);        // one STS.64
        __syncthreads();

        // prefetch next input (hidden under matvec)
        if (s + 1 < S_LEN)
            x = xg[((size_t)(b0 + g) * S_LEN + (s + 1)) * HD + e];

        // ---- matvec over own k-quarter, all 4 rows, 4 independent chains ----
        unsigned long long pac0 = 0ull, pac1 = 0ull, pac2 = 0ull, pac3 = 0ull;
        const ulonglong2 *pA = s01 + g * KQ;
        const ulonglong2 *pB = s23 + g * KQ;
#pragma unroll
        for (int j = 0; j < KQ; ++j) {
            ulonglong2 v01 = pA[j];    // {h0,x0,h1,x1} broadcast LDS.128
            ulonglong2 v23 = pB[j];
            pac0 = fma2(wu[j], v01.x, pac0);   // {W*h0, U*x0}
            pac1 = fma2(wu[j], v01.y, pac1);
            pac2 = fma2(wu[j], v23.x, pac2);
            pac3 = fma2(wu[j], v23.y, pac3);
        }
        ulonglong2 q01, q23;
        q01.x = pac0; q01.y = pac1;
        q23.x = pac2; q23.y = pac3;
        ps[g][e][0] = q01;             // two STS.128
        ps[g][e][1] = q23;
        __syncthreads();

        // ---- reduce 4 k-quarter partials for own row g ----
        const unsigned long long *col0 = ((const unsigned long long *)ps[0][e]) + g;
        const unsigned long long *col1 = ((const unsigned long long *)ps[1][e]) + g;
        const unsigned long long *col2 = ((const unsigned long long *)ps[2][e]) + g;
        const unsigned long long *col3 = ((const unsigned long long *)ps[3][e]) + g;
        unsigned long long acc = add2(add2(*col0, *col1), add2(*col2, *col3));
        float wacc, uacc;
        unpack2f(acc, wacc, uacc);

        float o = step_row(wacc, hn, uacc, xn, bia, bip);

        yg[((size_t)(b0 + g) * S_LEN + s) * HD + e] = o;
        h = o;
    }
}

extern "C" void kernel_launch(void *const *d_in, const int *in_sizes, int n_in,
                              void *d_out, int out_size) {
    const float *xg = (const float *)d_in[0];   // inputs [512,512,64,2]
    const float *wg = (const float *)d_in[1];   // w [64,2,64,2] -> [128,128]
    const float *ug = (const float *)d_in[2];   // u
    const float *bg = (const float *)d_in[3];   // b [64,2]
    float *yg = (float *)d_out;

    hyper_rnn_kernel<<<BATCH / NB, NTHR>>>(xg, wg, ug, bg, yg);
}